// round 13
// baseline (speedup 1.0000x reference)
#include <cuda_runtime.h>
#include <cuda_fp16.h>

typedef unsigned int u32;
typedef unsigned short u16;

// LocalDeepRFMFull via mma.sync m16n8k16 fp16 (plain sm_103 PTX).
// 1 batch row/CTA, 8 warps (4m x 2n grid, m32 x n128 per warp), 2 CTAs/SM.
// Single-pass fp16 main GEMM (Ah*Bh), single-pass z-GEMM (h*Woh).
// B fragments double-buffered at k16-chunk granularity across the full
// warp-stage (prefetch spans nc boundaries -> epilogue overlaps next
// mainloop's LDS latency). d initialized with bias; packed fp16x2 tanh.
// B/Wo images prebuilt in gmem, staged per stage via cp.async.

#define TPB       256
#define NSTAGE    4
#define A_STRIDE  176               // 80 fp16 cols + pad -> 11 x 16B (conflict-free ldmatrix)
#define A_BYTES   (128*A_STRIDE)    // 22528
#define B_STRIDE  176
#define B_BYTES   (256*B_STRIDE)    // 45056
#define WO_STRIDE 528               // 256 fp16 cols + pad -> 33 x 16B
#define WO_BYTES  (8*WO_STRIDE)     // 4224
#define SMEM_TOTAL (A_BYTES + B_BYTES + WO_BYTES + 2*1024*4 + 256*4)  // 81024

// Prebuilt fp16 Wi image (cols 0..79) and Wo-hi image, per stage.
__device__ __align__(16) unsigned char g_Bimg[NSTAGE][B_BYTES];
__device__ __align__(16) unsigned char g_Wimg[NSTAGE][WO_BYTES];

__device__ __forceinline__ u32 smem_u32(const void* p) {
    u32 a;
    asm("{ .reg .u64 t; cvta.to.shared.u64 t, %1; cvt.u32.u64 %0, t; }" : "=r"(a) : "l"(p));
    return a;
}
// pack: low half = fp16(lo), high half = fp16(hi)
__device__ __forceinline__ u32 pack2(float lo, float hi) {
    __half2 h = __floats2half2_rn(lo, hi);
    return *(u32*)&h;
}

#define LDSM4(R0,R1,R2,R3,ADDR) \
    asm volatile("ldmatrix.sync.aligned.m8n8.x4.shared.b16 {%0,%1,%2,%3}, [%4];" \
        : "=r"(R0),"=r"(R1),"=r"(R2),"=r"(R3) : "r"(ADDR))
#define LDSM2(R0,R1,ADDR) \
    asm volatile("ldmatrix.sync.aligned.m8n8.x2.shared.b16 {%0,%1}, [%2];" \
        : "=r"(R0),"=r"(R1) : "r"(ADDR))
// non-volatile: pure register op, ptxas schedules freely
#define MMA(D,A0,A1,A2,A3,B0,B1) \
    asm("mma.sync.aligned.m16n8k16.row.col.f32.f16.f16.f32 " \
        "{%0,%1,%2,%3}, {%4,%5,%6,%7}, {%8,%9}, {%0,%1,%2,%3};" \
        : "+f"((D)[0]),"+f"((D)[1]),"+f"((D)[2]),"+f"((D)[3]) \
        : "r"(A0),"r"(A1),"r"(A2),"r"(A3),"r"(B0),"r"(B1))
#define TANH2(R) asm("tanh.approx.f16x2 %0, %0;" : "+r"(R))
#define CPA16(DST, SRC) \
    asm volatile("cp.async.cg.shared.global [%0], [%1], 16;" :: "r"(DST), "l"(SRC) : "memory")

// ---------------- precompute: Wi fp16 image + Wo-hi image ----------------
__global__ void build_imgs_kernel(const float* __restrict__ Wi,
                                  const float* __restrict__ Wo) {
    const int s = blockIdx.x, r = threadIdx.x;
    const float* w = Wi + (size_t)(s * 256 + r) * 80;
    unsigned char* img = g_Bimg[s] + r * B_STRIDE;
    for (int c = 0; c < 80; c += 2)
        *(u32*)(img + 2 * c) = pack2(w[c], w[c + 1]);
    unsigned char* wim = g_Wimg[s];
    for (int c = 0; c < 8; ++c) {
        __half hh = __float2half_rn(Wo[(size_t)s * 2048 + c * 256 + r]);
        *(u16*)(wim + c * WO_STRIDE + 2 * r) = *(u16*)&hh;
    }
}

// ---------------- main kernel ----------------
__global__ void __launch_bounds__(TPB, 2)
rfm_mma_kernel(const float* __restrict__ x, const float* __restrict__ bi,
               float* __restrict__ out)
{
    extern __shared__ __align__(16) unsigned char smem[];
    unsigned char* A_sm  = smem;                       // 128 x 80 fp16: xh(40)|zh(40)
    unsigned char* B_sm  = smem + A_BYTES;             // 256 x 80 fp16: Wi hi
    unsigned char* WO_sm = smem + A_BYTES + B_BYTES;   // 8 x 256 fp16: Wo hi
    float* ZP = (float*)(WO_sm + WO_BYTES);            // [2][1024] z partials
    float* BI = ZP + 2 * 1024;                         // [256]

    const int t = threadIdx.x, w = t >> 5, lane = t & 31;
    const int wm = w & 3, wn = w >> 2;                 // 4 x 2 warp grid
    const int rr = lane & 7, q = lane >> 3;

    const u32 A32 = smem_u32(A_sm), B32 = smem_u32(B_sm), W32 = smem_u32(WO_sm);

    // m32 tile per warp: rows 32*wm .. 32*wm+31
    const u32 aT = A32 + (u32)((32 * wm + rr + 8 * (q & 1)) * A_STRIDE + (q >> 1) * 16);
    const u32 bT = B32 + (u32)((rr + 8 * (q >> 1)) * B_STRIDE + (q & 1) * 16)
                 + (u32)(wn * 4 * 32 * B_STRIDE);      // this warp's n-half base
    const u32 wT = W32 + (u32)(rr * WO_STRIDE + (q & 1) * 16);

    // ---- init A: x window -> xh cols 0..39 AND zh cols 40..79 (z starts = x) ----
    const float* xr = x + (size_t)blockIdx.x * 1024;
    for (int idx = t; idx < 128 * 20; idx += TPB) {
        int g = idx / 20, p = idx - g * 20;
        int basei = (8 * g - 16 + 2 * p) & 1023;  // even -> pair never wraps
        u32 hp = pack2(xr[basei], xr[basei + 1]);
        unsigned char* arow = A_sm + g * A_STRIDE;
        *(u32*)(arow + 4 * p)      = hp;   // x hi
        *(u32*)(arow + 80 + 4 * p) = hp;   // z hi
    }

    for (int s = 0; s < NSTAGE; ++s) {
        // B + Wo image stage-in via cp.async (L2-resident across CTAs)
        {
            const char* bsrc = (const char*)&g_Bimg[s][0];
            for (int i = t; i < B_BYTES / 16; i += TPB)
                CPA16(B32 + 16 * i, bsrc + 16 * i);
            const char* wsrc = (const char*)&g_Wimg[s][0];
            for (int i = t; i < WO_BYTES / 16; i += TPB)
                CPA16(W32 + 16 * i, wsrc + 16 * i);
            asm volatile("cp.async.commit_group;" ::: "memory");
        }
        BI[t] = bi[s * 256 + t];
        // A z-cols from ZP partial sums (stages 1..3)
        if (s > 0) {
            for (int idx = t; idx < 128 * 20; idx += TPB) {
                int g = idx / 20, p = idx - g * 20;
                int basei = (8 * g - 16 + 2 * p) & 1023;
                float v0 = ZP[basei]     + ZP[1024 + basei];
                float v1 = ZP[basei + 1] + ZP[1024 + basei + 1];
                *(u32*)(A_sm + g * A_STRIDE + 80 + 4 * p) = pack2(v0, v1);
            }
        }
        asm volatile("cp.async.wait_group 0;" ::: "memory");
        __syncthreads();

        // ---- hoist A fragments: 2 m-tiles x 5 k16-chunks = 40 regs ----
        u32 A[2][5][4];
        #pragma unroll
        for (int mt = 0; mt < 2; ++mt)
            #pragma unroll
            for (int ch = 0; ch < 5; ++ch)
                LDSM4(A[mt][ch][0], A[mt][ch][1], A[mt][ch][2], A[mt][ch][3],
                      aT + (u32)(mt * 16 * A_STRIDE + ch * 32));

        float zacc[2][4] = {{0,0,0,0},{0,0,0,0}};

        // ---- software-pipelined mainloop: double-buffered B fragments ----
        u32 Bp[2][4], Br[2][4];
        LDSM4(Bp[0][0], Bp[0][1], Bp[0][2], Bp[0][3], bT);
        LDSM4(Br[0][0], Br[0][1], Br[0][2], Br[0][3], bT + 16 * B_STRIDE);

        #pragma unroll
        for (int inc = 0; inc < 4; ++inc) {
            const int nc = 4 * wn + inc;
            const u32 bBase = bT + (u32)(inc * 32 * B_STRIDE);

            // d initialized with bias (saves the epilogue FADDs)
            float d[2][4][4];
            #pragma unroll
            for (int j = 0; j < 4; ++j) {
                const int lc = nc * 32 + j * 8 + 2 * (lane & 3);
                float2 bp = *(const float2*)&BI[lc];
                #pragma unroll
                for (int mt = 0; mt < 2; ++mt) {
                    d[mt][j][0] = bp.x; d[mt][j][1] = bp.y;
                    d[mt][j][2] = bp.x; d[mt][j][3] = bp.y;
                }
            }

            #pragma unroll
            for (int ch = 0; ch < 5; ++ch) {
                const int cur = (inc * 5 + ch) & 1, nxt = cur ^ 1;
                // prefetch next chunk (or next inc's chunk0) before this chunk's MMAs
                if (ch < 4) {
                    LDSM4(Bp[nxt][0], Bp[nxt][1], Bp[nxt][2], Bp[nxt][3],
                          bBase + (ch + 1) * 32);
                    LDSM4(Br[nxt][0], Br[nxt][1], Br[nxt][2], Br[nxt][3],
                          bBase + 16 * B_STRIDE + (ch + 1) * 32);
                } else if (inc < 3) {
                    LDSM4(Bp[nxt][0], Bp[nxt][1], Bp[nxt][2], Bp[nxt][3],
                          bBase + 32 * B_STRIDE);
                    LDSM4(Br[nxt][0], Br[nxt][1], Br[nxt][2], Br[nxt][3],
                          bBase + 48 * B_STRIDE);
                }
                #pragma unroll
                for (int mt = 0; mt < 2; ++mt) {
                    MMA(d[mt][0], A[mt][ch][0],A[mt][ch][1],A[mt][ch][2],A[mt][ch][3],
                        Bp[cur][0],Bp[cur][1]);
                    MMA(d[mt][1], A[mt][ch][0],A[mt][ch][1],A[mt][ch][2],A[mt][ch][3],
                        Bp[cur][2],Bp[cur][3]);
                    MMA(d[mt][2], A[mt][ch][0],A[mt][ch][1],A[mt][ch][2],A[mt][ch][3],
                        Br[cur][0],Br[cur][1]);
                    MMA(d[mt][3], A[mt][ch][0],A[mt][ch][1],A[mt][ch][2],A[mt][ch][3],
                        Br[cur][2],Br[cur][3]);
                }
            }

            // Wo-hi fragments for this k-slice (issued while next-inc chunk0 flies)
            u32 bh0a,bh0b,bh1a,bh1b;
            LDSM2(bh0a,bh0b, wT + (u32)(nc * 64));
            LDSM2(bh1a,bh1b, wT + (u32)(nc * 64 + 32));

            // ---- epilogue per m-tile: pack, fp16x2 tanh, z-MMA (Wo-hi only) ----
            #pragma unroll
            for (int mt = 0; mt < 2; ++mt) {
                u32 h[8];
                #pragma unroll
                for (int j = 0; j < 4; ++j) {
                    u32 hp0 = pack2(d[mt][j][0], d[mt][j][1]);
                    u32 hp1 = pack2(d[mt][j][2], d[mt][j][3]);
                    TANH2(hp0); TANH2(hp1);
                    h[2*j] = hp0; h[2*j+1] = hp1;
                }
                MMA(zacc[mt], h[0],h[1],h[2],h[3], bh0a,bh0b);
                MMA(zacc[mt], h[4],h[5],h[6],h[7], bh1a,bh1b);
            }
        }

        // ---- stage end: store z partials (flat idx = g*8+c) ----
        {
            float* zp = ZP + wn * 1024;
            const int c0 = 2 * (lane & 3);
            #pragma unroll
            for (int mt = 0; mt < 2; ++mt) {
                const int g = 32 * wm + 16 * mt + (lane >> 2);
                *(float2*)&zp[g * 8 + c0]       = make_float2(zacc[mt][0], zacc[mt][1]);
                *(float2*)&zp[(g + 8) * 8 + c0] = make_float2(zacc[mt][2], zacc[mt][3]);
            }
        }
        __syncthreads();   // ZP ready; also guards A/B/WO_sm rewrite next stage
    }

    // ---- final output: out = ZP0 + ZP1 ----
    float* orow = out + (size_t)blockIdx.x * 1024;
    for (int i = t; i < 1024; i += TPB)
        orow[i] = ZP[i] + ZP[1024 + i];
}

extern "C" void kernel_launch(void* const* d_in, const int* in_sizes, int n_in,
                              void* d_out, int out_size)
{
    const float* x  = (const float*)d_in[0];   // [4096, 1024]
    const float* Wi = (const float*)d_in[1];   // [4, 256, 80]
    const float* bi = (const float*)d_in[2];   // [4, 256]
    const float* Wo = (const float*)d_in[3];   // [4, 8, 256]
    float* out = (float*)d_out;                // [4096, 1024]

    cudaFuncSetAttribute(rfm_mma_kernel, cudaFuncAttributeMaxDynamicSharedMemorySize, SMEM_TOTAL);

    build_imgs_kernel<<<NSTAGE, 256>>>(Wi, Wo);
    const int nrows = in_sizes[0] / 1024;
    rfm_mma_kernel<<<nrows, TPB, SMEM_TOTAL>>>(x, bi, out);
}

// round 14
// speedup vs baseline: 1.5514x; 1.5514x over previous
#include <cuda_runtime.h>
#include <cuda_fp16.h>

typedef unsigned int u32;
typedef unsigned short u16;

// LocalDeepRFMFull via mma.sync m16n8k16 fp16 (plain sm_103 PTX).
// 1 batch row/CTA, 8 warps (4m x 2n grid, m32 x n128 per warp), 2 CTAs/SM.
// Single-pass fp16 main GEMM (Ah*Bh), single-pass z-GEMM (h*Woh).
// Per nc, each n16-half's 5 LDSM4 are batch-issued (MLP=5) before their MMAs
// (no cross-iteration buffering -- R13's parity pipeline regressed).
// d initialized with bias; packed fp16x2 tanh. B/Wo images prebuilt in gmem,
// staged per stage via cp.async.

#define TPB       256
#define NSTAGE    4
#define A_STRIDE  176               // 80 fp16 cols + pad -> 11 x 16B (conflict-free ldmatrix)
#define A_BYTES   (128*A_STRIDE)    // 22528
#define B_STRIDE  176
#define B_BYTES   (256*B_STRIDE)    // 45056
#define WO_STRIDE 528               // 256 fp16 cols + pad -> 33 x 16B
#define WO_BYTES  (8*WO_STRIDE)     // 4224
#define SMEM_TOTAL (A_BYTES + B_BYTES + WO_BYTES + 2*1024*4 + 256*4)  // 81024

// Prebuilt fp16 Wi image (cols 0..79) and Wo-hi image, per stage.
__device__ __align__(16) unsigned char g_Bimg[NSTAGE][B_BYTES];
__device__ __align__(16) unsigned char g_Wimg[NSTAGE][WO_BYTES];

__device__ __forceinline__ u32 smem_u32(const void* p) {
    u32 a;
    asm("{ .reg .u64 t; cvta.to.shared.u64 t, %1; cvt.u32.u64 %0, t; }" : "=r"(a) : "l"(p));
    return a;
}
// pack: low half = fp16(lo), high half = fp16(hi)
__device__ __forceinline__ u32 pack2(float lo, float hi) {
    __half2 h = __floats2half2_rn(lo, hi);
    return *(u32*)&h;
}

#define LDSM4(R0,R1,R2,R3,ADDR) \
    asm volatile("ldmatrix.sync.aligned.m8n8.x4.shared.b16 {%0,%1,%2,%3}, [%4];" \
        : "=r"(R0),"=r"(R1),"=r"(R2),"=r"(R3) : "r"(ADDR))
#define LDSM2(R0,R1,ADDR) \
    asm volatile("ldmatrix.sync.aligned.m8n8.x2.shared.b16 {%0,%1}, [%2];" \
        : "=r"(R0),"=r"(R1) : "r"(ADDR))
// non-volatile: pure register op, ptxas schedules freely
#define MMA(D,A0,A1,A2,A3,B0,B1) \
    asm("mma.sync.aligned.m16n8k16.row.col.f32.f16.f16.f32 " \
        "{%0,%1,%2,%3}, {%4,%5,%6,%7}, {%8,%9}, {%0,%1,%2,%3};" \
        : "+f"((D)[0]),"+f"((D)[1]),"+f"((D)[2]),"+f"((D)[3]) \
        : "r"(A0),"r"(A1),"r"(A2),"r"(A3),"r"(B0),"r"(B1))
#define TANH2(R) asm("tanh.approx.f16x2 %0, %0;" : "+r"(R))
#define CPA16(DST, SRC) \
    asm volatile("cp.async.cg.shared.global [%0], [%1], 16;" :: "r"(DST), "l"(SRC) : "memory")

// ---------------- precompute: Wi fp16 image + Wo-hi image ----------------
__global__ void build_imgs_kernel(const float* __restrict__ Wi,
                                  const float* __restrict__ Wo) {
    const int s = blockIdx.x, r = threadIdx.x;
    const float* w = Wi + (size_t)(s * 256 + r) * 80;
    unsigned char* img = g_Bimg[s] + r * B_STRIDE;
    for (int c = 0; c < 80; c += 2)
        *(u32*)(img + 2 * c) = pack2(w[c], w[c + 1]);
    unsigned char* wim = g_Wimg[s];
    for (int c = 0; c < 8; ++c) {
        __half hh = __float2half_rn(Wo[(size_t)s * 2048 + c * 256 + r]);
        *(u16*)(wim + c * WO_STRIDE + 2 * r) = *(u16*)&hh;
    }
}

// ---------------- main kernel ----------------
__global__ void __launch_bounds__(TPB, 2)
rfm_mma_kernel(const float* __restrict__ x, const float* __restrict__ bi,
               float* __restrict__ out)
{
    extern __shared__ __align__(16) unsigned char smem[];
    unsigned char* A_sm  = smem;                       // 128 x 80 fp16: xh(40)|zh(40)
    unsigned char* B_sm  = smem + A_BYTES;             // 256 x 80 fp16: Wi hi
    unsigned char* WO_sm = smem + A_BYTES + B_BYTES;   // 8 x 256 fp16: Wo hi
    float* ZP = (float*)(WO_sm + WO_BYTES);            // [2][1024] z partials
    float* BI = ZP + 2 * 1024;                         // [256]

    const int t = threadIdx.x, w = t >> 5, lane = t & 31;
    const int wm = w & 3, wn = w >> 2;                 // 4 x 2 warp grid
    const int rr = lane & 7, q = lane >> 3;

    const u32 A32 = smem_u32(A_sm), B32 = smem_u32(B_sm), W32 = smem_u32(WO_sm);

    // m32 tile per warp: rows 32*wm .. 32*wm+31
    const u32 aT = A32 + (u32)((32 * wm + rr + 8 * (q & 1)) * A_STRIDE + (q >> 1) * 16);
    const u32 bT = B32 + (u32)((rr + 8 * (q >> 1)) * B_STRIDE + (q & 1) * 16);
    const u32 wT = W32 + (u32)(rr * WO_STRIDE + (q & 1) * 16);

    // ---- init A: x window -> xh cols 0..39 AND zh cols 40..79 (z starts = x) ----
    const float* xr = x + (size_t)blockIdx.x * 1024;
    for (int idx = t; idx < 128 * 20; idx += TPB) {
        int g = idx / 20, p = idx - g * 20;
        int basei = (8 * g - 16 + 2 * p) & 1023;  // even -> pair never wraps
        u32 hp = pack2(xr[basei], xr[basei + 1]);
        unsigned char* arow = A_sm + g * A_STRIDE;
        *(u32*)(arow + 4 * p)      = hp;   // x hi
        *(u32*)(arow + 80 + 4 * p) = hp;   // z hi
    }

    for (int s = 0; s < NSTAGE; ++s) {
        // B + Wo image stage-in via cp.async (L2-resident across CTAs)
        {
            const char* bsrc = (const char*)&g_Bimg[s][0];
            for (int i = t; i < B_BYTES / 16; i += TPB)
                CPA16(B32 + 16 * i, bsrc + 16 * i);
            const char* wsrc = (const char*)&g_Wimg[s][0];
            for (int i = t; i < WO_BYTES / 16; i += TPB)
                CPA16(W32 + 16 * i, wsrc + 16 * i);
            asm volatile("cp.async.commit_group;" ::: "memory");
        }
        BI[t] = bi[s * 256 + t];
        // A z-cols from ZP partial sums (stages 1..3)
        if (s > 0) {
            for (int idx = t; idx < 128 * 20; idx += TPB) {
                int g = idx / 20, p = idx - g * 20;
                int basei = (8 * g - 16 + 2 * p) & 1023;
                float v0 = ZP[basei]     + ZP[1024 + basei];
                float v1 = ZP[basei + 1] + ZP[1024 + basei + 1];
                *(u32*)(A_sm + g * A_STRIDE + 80 + 4 * p) = pack2(v0, v1);
            }
        }
        asm volatile("cp.async.wait_group 0;" ::: "memory");
        __syncthreads();

        // ---- hoist A fragments: 2 m-tiles x 5 k16-chunks = 40 regs ----
        u32 A[2][5][4];
        #pragma unroll
        for (int mt = 0; mt < 2; ++mt)
            #pragma unroll
            for (int ch = 0; ch < 5; ++ch)
                LDSM4(A[mt][ch][0], A[mt][ch][1], A[mt][ch][2], A[mt][ch][3],
                      aT + (u32)(mt * 16 * A_STRIDE + ch * 32));

        float zacc[2][4] = {{0,0,0,0},{0,0,0,0}};

        // ---- this warp's 4 n-chunks: nc = 4*wn + inc ----
        #pragma unroll
        for (int inc = 0; inc < 4; ++inc) {
            const int nc = 4 * wn + inc;
            const u32 bBase = bT + (u32)(nc * 32 * B_STRIDE);

            // ---- n16-half 0: batch 5 LDSM4 (MLP=5), then 20 MMAs ----
            u32 Bf[5][4];
            #pragma unroll
            for (int ch = 0; ch < 5; ++ch)
                LDSM4(Bf[ch][0], Bf[ch][1], Bf[ch][2], Bf[ch][3], bBase + ch * 32);

            // d initialized with bias (fills the LDSM shadow)
            float d[2][4][4];
            #pragma unroll
            for (int j = 0; j < 4; ++j) {
                const int lc = nc * 32 + j * 8 + 2 * (lane & 3);
                float2 bp = *(const float2*)&BI[lc];
                #pragma unroll
                for (int mt = 0; mt < 2; ++mt) {
                    d[mt][j][0] = bp.x; d[mt][j][1] = bp.y;
                    d[mt][j][2] = bp.x; d[mt][j][3] = bp.y;
                }
            }

            #pragma unroll
            for (int ch = 0; ch < 5; ++ch)
                #pragma unroll
                for (int mt = 0; mt < 2; ++mt) {
                    MMA(d[mt][0], A[mt][ch][0],A[mt][ch][1],A[mt][ch][2],A[mt][ch][3],
                        Bf[ch][0],Bf[ch][1]);
                    MMA(d[mt][1], A[mt][ch][0],A[mt][ch][1],A[mt][ch][2],A[mt][ch][3],
                        Bf[ch][2],Bf[ch][3]);
                }

            // ---- n16-half 1: batch 5 LDSM4, Wo frags in the shadow, 20 MMAs ----
            u32 Bg[5][4];
            #pragma unroll
            for (int ch = 0; ch < 5; ++ch)
                LDSM4(Bg[ch][0], Bg[ch][1], Bg[ch][2], Bg[ch][3],
                      bBase + 16 * B_STRIDE + ch * 32);

            u32 bh0a,bh0b,bh1a,bh1b;
            LDSM2(bh0a,bh0b, wT + (u32)(nc * 64));
            LDSM2(bh1a,bh1b, wT + (u32)(nc * 64 + 32));

            #pragma unroll
            for (int ch = 0; ch < 5; ++ch)
                #pragma unroll
                for (int mt = 0; mt < 2; ++mt) {
                    MMA(d[mt][2], A[mt][ch][0],A[mt][ch][1],A[mt][ch][2],A[mt][ch][3],
                        Bg[ch][0],Bg[ch][1]);
                    MMA(d[mt][3], A[mt][ch][0],A[mt][ch][1],A[mt][ch][2],A[mt][ch][3],
                        Bg[ch][2],Bg[ch][3]);
                }

            // ---- epilogue per m-tile: pack, fp16x2 tanh, z-MMA (Wo-hi only) ----
            #pragma unroll
            for (int mt = 0; mt < 2; ++mt) {
                u32 h[8];
                #pragma unroll
                for (int j = 0; j < 4; ++j) {
                    u32 hp0 = pack2(d[mt][j][0], d[mt][j][1]);
                    u32 hp1 = pack2(d[mt][j][2], d[mt][j][3]);
                    TANH2(hp0); TANH2(hp1);
                    h[2*j] = hp0; h[2*j+1] = hp1;
                }
                MMA(zacc[mt], h[0],h[1],h[2],h[3], bh0a,bh0b);
                MMA(zacc[mt], h[4],h[5],h[6],h[7], bh1a,bh1b);
            }
        }

        // ---- stage end: store z partials (flat idx = g*8+c) ----
        {
            float* zp = ZP + wn * 1024;
            const int c0 = 2 * (lane & 3);
            #pragma unroll
            for (int mt = 0; mt < 2; ++mt) {
                const int g = 32 * wm + 16 * mt + (lane >> 2);
                *(float2*)&zp[g * 8 + c0]       = make_float2(zacc[mt][0], zacc[mt][1]);
                *(float2*)&zp[(g + 8) * 8 + c0] = make_float2(zacc[mt][2], zacc[mt][3]);
            }
        }
        __syncthreads();   // ZP ready; also guards A/B/WO_sm rewrite next stage
    }

    // ---- final output: out = ZP0 + ZP1 ----
    float* orow = out + (size_t)blockIdx.x * 1024;
    for (int i = t; i < 1024; i += TPB)
        orow[i] = ZP[i] + ZP[1024 + i];
}

extern "C" void kernel_launch(void* const* d_in, const int* in_sizes, int n_in,
                              void* d_out, int out_size)
{
    const float* x  = (const float*)d_in[0];   // [4096, 1024]
    const float* Wi = (const float*)d_in[1];   // [4, 256, 80]
    const float* bi = (const float*)d_in[2];   // [4, 256]
    const float* Wo = (const float*)d_in[3];   // [4, 8, 256]
    float* out = (float*)d_out;                // [4096, 1024]

    cudaFuncSetAttribute(rfm_mma_kernel, cudaFuncAttributeMaxDynamicSharedMemorySize, SMEM_TOTAL);

    build_imgs_kernel<<<NSTAGE, 256>>>(Wi, Wo);
    const int nrows = in_sizes[0] / 1024;
    rfm_mma_kernel<<<nrows, TPB, SMEM_TOTAL>>>(x, bi, out);
}